// round 16
// baseline (speedup 1.0000x reference)
#include <cuda_runtime.h>
#include <cuda_bf16.h>
#include <math.h>
#include <stdint.h>

// ---------------- compile-time config ----------------
#define ROWS 32          // B (queries)
#define DMAX 1024
#define MAXSEL 1024
#define EQCAP 256
#define NBIN 4096
#define HCH 64
#define CAND 8192

// mma GEMM tiling
#define TN 64            // keys per CTA (4 CTAs/SM)
#define KC 64            // dims per chunk
#define ASW2 72          // A chunk smem row stride (bf16): 36 words = 4 mod 32 -> LDSM conflict-free
#define KSW 72           // key smem row stride (bf16)
#define A_CH_BYTES (64 * ASW2 * 2)      // 9216
#define KMAT_BYTES (TN * KSW * 2)       // 9216
#define STAGE_B (A_CH_BYTES + 2 * KMAT_BYTES)   // 27648
#define GEMM2_DYN (2 * STAGE_B + 256)           // 55552 -> 4 CTAs/SM

typedef unsigned long long ull;

// ---------------- scratch (device globals; no runtime allocation) ----------------
__device__ float g_pooled[ROWS * DMAX];
__device__ __nv_bfloat16 g_ab[64 * DMAX];        // rows 0-31: qh, rows 32-63: ql
__device__ float g_scores[(size_t)ROWS * 500224];
__device__ float g_sel_score[ROWS * MAXSEL];
__device__ int   g_sel_idx[ROWS * MAXSEL];
__device__ unsigned g_hist[ROWS][NBIN];
__device__ unsigned g_thr[ROWS];
__device__ int      g_ccnt[ROWS];
__device__ float    g_cscore[ROWS * CAND];
__device__ int      g_cidx[ROWS * CAND];

// ---------------- helpers ----------------
__device__ __forceinline__ void cpa16(void* dst_smem, const void* src) {
    unsigned s = (unsigned)__cvta_generic_to_shared(dst_smem);
    asm volatile("cp.async.cg.shared.global [%0], [%1], 16;" :: "r"(s), "l"(src) : "memory");
}
__device__ __forceinline__ void cp_commit() { asm volatile("cp.async.commit_group;" ::: "memory"); }
__device__ __forceinline__ void cp_wait0()  { asm volatile("cp.async.wait_group 0;" ::: "memory"); }

__device__ __forceinline__ unsigned flipf(float f) {
    unsigned u = __float_as_uint(f);
    return (u & 0x80000000u) ? ~u : (u | 0x80000000u);
}
__device__ __forceinline__ float unflipf(unsigned u) {
    return __uint_as_float((u & 0x80000000u) ? (u ^ 0x80000000u) : ~u);
}
__device__ __forceinline__ int eff_k(const int* kptr, const int* mkptr) {
    int k = kptr[0];
    int mk = mkptr[0];
    if (mk < k) k = mk;
    if (k < 1) k = 1;
    if (k > MAXSEL) k = MAXSEL;
    return k;
}
// pack two fp32 -> bf16x2, f0 in low half (element order)
__device__ __forceinline__ uint32_t pk_bf(float f0, float f1) {
    uint32_t r;
    asm("cvt.rn.bf16x2.f32 %0, %1, %2;" : "=r"(r) : "f"(f1), "f"(f0));
    return r;
}
__device__ __forceinline__ float bf_lo(uint32_t w) { return __uint_as_float(w << 16); }
__device__ __forceinline__ float bf_hi(uint32_t w) { return __uint_as_float(w & 0xFFFF0000u); }

// bf16 m16n8k16 tensor-core MMA
__device__ __forceinline__ void mma16816(float* c, const uint32_t* a, const uint32_t* b) {
    asm volatile("mma.sync.aligned.m16n8k16.row.col.f32.bf16.bf16.f32 "
                 "{%0,%1,%2,%3}, {%4,%5,%6,%7}, {%8,%9}, {%0,%1,%2,%3};"
                 : "+f"(c[0]), "+f"(c[1]), "+f"(c[2]), "+f"(c[3])
                 : "r"(a[0]), "r"(a[1]), "r"(a[2]), "r"(a[3]), "r"(b[0]), "r"(b[1]));
}
__device__ __forceinline__ void ldsm4(uint32_t* r, uint32_t addr) {
    asm volatile("ldmatrix.sync.aligned.m8n8.x4.shared.b16 {%0,%1,%2,%3}, [%4];"
                 : "=r"(r[0]), "=r"(r[1]), "=r"(r[2]), "=r"(r[3]) : "r"(addr));
}

// ---------------- K1a: pooled = mean(hidden, axis=T) ----------------
__global__ __launch_bounds__(256) void pool_mean_kernel(
    const float* __restrict__ hidden, int B, int T, int D)
{
    int gt = blockIdx.x * blockDim.x + threadIdx.x;
    if (gt >= B * D) return;
    int b = gt / D;
    int d = gt - b * D;
    const float* p = hidden + (size_t)b * T * D + d;
    float s = 0.f;
    #pragma unroll 8
    for (int t = 0; t < T; t++) s += p[(size_t)t * D];
    g_pooled[gt] = s * (1.0f / (float)T);
}

// ---------------- K1b: query = pooled @ W + bias, split bf16 hi/lo -> g_ab ----------------
__global__ __launch_bounds__(256) void query_projsplit_kernel(
    const float* __restrict__ W, const float* __restrict__ bias, int D)
{
    int b = blockIdx.x;
    int tid = threadIdx.x;
    __shared__ float sp[DMAX];
    for (int i = tid; i < D; i += blockDim.x) sp[i] = g_pooled[b * D + i];
    __syncthreads();
    for (int d = tid; d < D; d += blockDim.x) {
        float a = bias[d];
        #pragma unroll 8
        for (int kx = 0; kx < D; kx++) a += sp[kx] * W[(size_t)kx * D + d];
        __nv_bfloat16 h = __float2bfloat16(a);
        g_ab[b * D + d] = h;
        g_ab[(b + 32) * D + d] = __float2bfloat16(a - __bfloat162float(h));
    }
}

// ---------------- K2: split-bf16 tensor-core score GEMM ----------------
// TN=64 keys x D per CTA, 4 CTAs/SM (32 warps; occupancy scaling law from
// R11->R13). A ([qh;ql], cp.async) + keys (LDG fp32 -> bf16 hi/lo -> STS.64,
// the R13-verified pattern) per KC=64 chunk, double-buffered, one sync/chunk.
// Warp tile: rows mt*16..+15, 2 ntiles (single ldmatrix.x4 pair). 3 MMAs per
// fragment (qh*kh, ql*kh, qh*kl) -> exact to ~1e-9.
extern __shared__ char gdyn[];
__global__ __launch_bounds__(256, 4) void gemm_mma_kernel(
    const float* __restrict__ keys, int N, int D, float scale)
{
    const int tid = threadIdx.x;
    const int lane = tid & 31;
    const int wid = tid >> 5;
    const int g = lane >> 2;        // 0..7
    const int tig = lane & 3;       // 0..3
    const int mt = wid >> 2;        // 0..1  (score rows mt*16..+15)
    const int nq = wid & 3;         // 0..3  (ntiles nq*2..+1)
    const long long nbase = (long long)blockIdx.x * TN;

    uint32_t raw;
    asm("{ .reg .u64 t; cvta.to.shared.u64 t, %1; cvt.u32.u64 %0, t; }" : "=r"(raw) : "l"(gdyn));
    char* base = gdyn + (((raw + 127u) & ~127u) - raw);
    const uint32_t base_u = (raw + 127u) & ~127u;

    __nv_bfloat16* Ast[2] = { (__nv_bfloat16*)base,
                              (__nv_bfloat16*)(base + STAGE_B) };
    __nv_bfloat16* KH[2]  = { (__nv_bfloat16*)(base + A_CH_BYTES),
                              (__nv_bfloat16*)(base + STAGE_B + A_CH_BYTES) };
    __nv_bfloat16* KL[2]  = { (__nv_bfloat16*)(base + A_CH_BYTES + KMAT_BYTES),
                              (__nv_bfloat16*)(base + STAGE_B + A_CH_BYTES + KMAT_BYTES) };

    const int nch = D / KC;

    // ldmatrix lane-role constants
    const int aquad = lane >> 3;
    const int arow  = (aquad & 1) * 8 + (lane & 7);
    const int akoff = (aquad >> 1) * 8;
    const uint32_t a_off  = ((mt * 16 + arow) * ASW2 + akoff) * 2;
    const uint32_t AQL_D  = 32 * ASW2 * 2;
    // B pair (tiles nq*2+0, nq*2+1) via x4: m order (t0,k0)(t0,k8)(t1,k0)(t1,k8)
    const int bm    = lane >> 3;
    const int btile = bm >> 1;
    const int bkoff = (bm & 1) * 8;
    const int brow  = lane & 7;
    const uint32_t b_off_pair =
        (((nq * 2 + btile) * 8 + brow) * KSW + bkoff) * 2;

    auto load_A = [&](int st, int c) {
        #pragma unroll
        for (int it = 0; it < 2; it++) {
            int slot = tid + it * 256;        // 0..511
            int row = slot >> 3;              // 0..63
            int c16 = slot & 7;
            cpa16((char*)(Ast[st] + row * ASW2) + c16 * 16,
                  g_ab + (size_t)row * D + c * KC + c16 * 8);
        }
        cp_commit();
    };

    float acc[2][4];
    #pragma unroll
    for (int t = 0; t < 2; t++)
        #pragma unroll
        for (int j = 0; j < 4; j++) acc[t][j] = 0.f;

    load_A(0, 0);

    for (int c = 0; c < nch; c++) {
        const int st = c & 1;
        const uint32_t su = base_u + st * STAGE_B;

        // LDG fp32 keys chunk c -> bf16 hi/lo -> STS.64 (R13 pattern; 1024 slots, 4/thread)
        #pragma unroll
        for (int it = 0; it < 4; it++) {
            int slot = tid + it * 256;        // 0..1023
            int row = slot >> 4;              // 0..63
            int q4  = slot & 15;              // float4 index in 64-col chunk
            long long grow = nbase + row;
            if (grow >= N) grow = N - 1;
            float4 v = *(const float4*)(keys + grow * (long long)D + c * KC + q4 * 4);
            uint32_t h0 = pk_bf(v.x, v.y);
            uint32_t h1 = pk_bf(v.z, v.w);
            uint32_t l0 = pk_bf(v.x - bf_lo(h0), v.y - bf_hi(h0));
            uint32_t l1 = pk_bf(v.z - bf_lo(h1), v.w - bf_hi(h1));
            char* dh = (char*)(KH[st] + row * KSW) + q4 * 8;
            char* dl = (char*)(KL[st] + row * KSW) + q4 * 8;
            *(uint2*)dh = make_uint2(h0, h1);
            *(uint2*)dl = make_uint2(l0, l1);
        }
        cp_wait0();        // own A(c) cp.asyncs done
        __syncthreads();   // one barrier: K(c)/A(c) visible; compute(c-1) done
        if (c + 1 < nch) load_A(st ^ 1, c + 1);

        // ---- compute chunk c ----
        const uint32_t kh_u = su + A_CH_BYTES;
        const uint32_t kl_u = kh_u + KMAT_BYTES;
        #pragma unroll
        for (int ks = 0; ks < KC / 16; ks++) {
            const uint32_t kb = ks * 32;
            uint32_t aqh[4], aql[4];
            ldsm4(aqh, su + a_off + kb);
            ldsm4(aql, su + a_off + AQL_D + kb);
            uint32_t bh[4], bl[4];
            ldsm4(bh, kh_u + b_off_pair + kb);
            ldsm4(bl, kl_u + b_off_pair + kb);
            mma16816(acc[0], aqh, bh + 0);
            mma16816(acc[0], aql, bh + 0);
            mma16816(acc[0], aqh, bl + 0);
            mma16816(acc[1], aqh, bh + 2);
            mma16816(acc[1], aql, bh + 2);
            mma16816(acc[1], aqh, bl + 2);
        }
    }

    // ---- epilogue: write scores ----
    #pragma unroll
    for (int t = 0; t < 2; t++) {
        const int nt = nq * 2 + t;
        long long col = nbase + nt * 8 + 2 * tig;
        int row0 = mt * 16 + g;
        if (col + 1 < N) {
            *(float2*)&g_scores[(size_t)row0 * N + col] =
                make_float2(acc[t][0] * scale, acc[t][1] * scale);
            *(float2*)&g_scores[(size_t)(row0 + 8) * N + col] =
                make_float2(acc[t][2] * scale, acc[t][3] * scale);
        } else if (col < N) {
            g_scores[(size_t)row0 * N + col] = acc[t][0] * scale;
            g_scores[(size_t)(row0 + 8) * N + col] = acc[t][2] * scale;
        }
    }
}

// ---------------- K3a: zero scratch ----------------
__global__ __launch_bounds__(256) void zero_scratch_kernel()
{
    int i = blockIdx.x * blockDim.x + threadIdx.x;
    if (i < ROWS * NBIN) ((unsigned*)g_hist)[i] = 0;
    if (i < ROWS) g_ccnt[i] = 0;
}

// ---------------- K3b: grid-parallel per-row histogram ----------------
__global__ __launch_bounds__(256) void hist_kernel(int N)
{
    const int r = blockIdx.y;
    const int c = blockIdx.x;
    const int tid = threadIdx.x;
    __shared__ unsigned sh[NBIN];
    for (int i = tid; i < NBIN; i += 256) sh[i] = 0;
    __syncthreads();

    const int per = (N + HCH - 1) / HCH;
    const int s = c * per;
    const int e = (s + per < N) ? s + per : N;
    const float* srow = g_scores + (size_t)r * N;
    for (int i = s + tid; i < e; i += 256)
        atomicAdd(&sh[flipf(srow[i]) >> 20], 1u);
    __syncthreads();

    for (int i = tid; i < NBIN; i += 256)
        if (sh[i]) atomicAdd(&g_hist[r][i], sh[i]);
}

// ---------------- K3c: per-row threshold bin ----------------
__global__ __launch_bounds__(256) void threshold_kernel(
    const int* __restrict__ kptr, const int* __restrict__ mkptr)
{
    const int r = blockIdx.x;
    const int tid = threadIdx.x;
    __shared__ unsigned h[NBIN];
    __shared__ unsigned sfx[257];
    __shared__ int selg;

    const int k = eff_k(kptr, mkptr);
    for (int i = tid; i < NBIN; i += 256) h[i] = g_hist[r][i];
    __syncthreads();

    unsigned gsum = 0;
    #pragma unroll
    for (int b = 0; b < 16; b++) gsum += h[tid * 16 + b];
    sfx[tid] = gsum;
    if (tid == 0) sfx[256] = 0;
    __syncthreads();
    for (int off = 1; off < 256; off <<= 1) {
        unsigned t = (tid + off < 256) ? sfx[tid + off] : 0u;
        __syncthreads();
        sfx[tid] += t;
        __syncthreads();
    }
    unsigned above = (tid < 255) ? sfx[tid + 1] : 0u;
    if ((int)above < k && (int)sfx[tid] >= k) selg = tid;
    __syncthreads();

    if (tid == 0) {
        int g = selg;
        unsigned cum = (g < 255) ? sfx[g + 1] : 0u;
        int bsel = g * 16;
        for (int b = g * 16 + 15; b >= g * 16; b--) {
            cum += h[b];
            if ((int)cum >= k) { bsel = b; break; }
        }
        g_thr[r] = ((unsigned)bsel) << 20;
    }
}

// ---------------- K3d: compaction ----------------
__global__ __launch_bounds__(256) void compact_kernel(int N)
{
    const int r = blockIdx.y;
    const int c = blockIdx.x;
    const int tid = threadIdx.x;
    const unsigned thr = g_thr[r];

    const int per = (N + HCH - 1) / HCH;
    const int s = c * per;
    const int e = (s + per < N) ? s + per : N;
    const float* srow = g_scores + (size_t)r * N;
    for (int i = s + tid; i < e; i += 256) {
        float v = srow[i];
        if (flipf(v) >= thr) {
            int p = atomicAdd(&g_ccnt[r], 1);
            if (p < CAND) {
                g_cscore[r * CAND + p] = v;
                g_cidx[r * CAND + p] = i;
            }
        }
    }
}

// ---------------- K3e: exact top-k over candidates ----------------
#define SEL_T 256
__global__ __launch_bounds__(SEL_T) void topk_final_kernel(
    const int* __restrict__ kptr, const int* __restrict__ mkptr)
{
    const int r = blockIdx.x;
    const int tid = threadIdx.x;
    int M = g_ccnt[r];
    if (M > CAND) M = CAND;
    int k = eff_k(kptr, mkptr);
    if (k > M) k = M;

    const float* cs = g_cscore + r * CAND;
    const int*   ci = g_cidx + r * CAND;

    __shared__ unsigned bins[256];
    __shared__ unsigned sfx[257];
    __shared__ unsigned sh_prefix;
    __shared__ int sh_need;
    __shared__ int sh_selv;

    if (tid == 0) { sh_prefix = 0; sh_need = k; }
    __syncthreads();

    for (int pass = 0; pass < 4; pass++) {
        const int shift = 24 - 8 * pass;
        const unsigned hmask = pass ? (0xFFFFFFFFu << (shift + 8)) : 0u;
        bins[tid] = 0;
        __syncthreads();
        const unsigned pref = sh_prefix;
        for (int i = tid; i < M; i += SEL_T) {
            unsigned u = flipf(cs[i]);
            if ((u & hmask) == pref)
                atomicAdd(&bins[(u >> shift) & 255u], 1u);
        }
        __syncthreads();
        sfx[tid] = bins[tid];
        if (tid == 0) sfx[256] = 0;
        __syncthreads();
        for (int off = 1; off < 256; off <<= 1) {
            unsigned t = (tid + off < 256) ? sfx[tid + off] : 0u;
            __syncthreads();
            sfx[tid] += t;
            __syncthreads();
        }
        const int need = sh_need;
        const unsigned above = (tid < 255) ? sfx[tid + 1] : 0u;
        if ((int)above < need && (int)sfx[tid] >= need)
            sh_selv = tid;
        __syncthreads();
        if (tid == 0) {
            int v = sh_selv;
            sh_need = need - (int)((v < 255) ? sfx[v + 1] : 0u);
            sh_prefix = pref | ((unsigned)v << shift);
        }
        __syncthreads();
    }

    const unsigned uk = sh_prefix;
    const int need = sh_need;

    __shared__ int cg, ce;
    __shared__ int eq[EQCAP];
    if (tid == 0) { cg = 0; ce = 0; }
    __syncthreads();

    for (int i = tid; i < M; i += SEL_T) {
        unsigned u = flipf(cs[i]);
        if (u > uk) {
            int p = atomicAdd(&cg, 1);
            g_sel_score[r * MAXSEL + p] = cs[i];
            g_sel_idx[r * MAXSEL + p] = ci[i];
        } else if (u == uk) {
            int p = atomicAdd(&ce, 1);
            if (p < EQCAP) eq[p] = ci[i];
        }
    }
    __syncthreads();

    if (tid == 0) {
        const float tie_score = unflipf(uk);
        int base = cg;
        int ne = ce < EQCAP ? ce : EQCAP;
        for (int t = 0; t < need; t++) {
            int mv = 0x7FFFFFFF, mi = -1;
            for (int j = 0; j < ne; j++)
                if (eq[j] < mv) { mv = eq[j]; mi = j; }
            if (mi >= 0) eq[mi] = 0x7FFFFFFF;
            g_sel_idx[r * MAXSEL + base + t] = mv;
            g_sel_score[r * MAXSEL + base + t] = tie_score;
        }
        for (int a = 0; a < k - 1; a++) {
            int best = a;
            for (int bidx = a + 1; bidx < k; bidx++)
                if (g_sel_idx[r * MAXSEL + bidx] < g_sel_idx[r * MAXSEL + best]) best = bidx;
            if (best != a) {
                int ti = g_sel_idx[r * MAXSEL + a];
                g_sel_idx[r * MAXSEL + a] = g_sel_idx[r * MAXSEL + best];
                g_sel_idx[r * MAXSEL + best] = ti;
                float ts = g_sel_score[r * MAXSEL + a];
                g_sel_score[r * MAXSEL + a] = g_sel_score[r * MAXSEL + best];
                g_sel_score[r * MAXSEL + best] = ts;
            }
        }
    }
}

// ---------------- K4: softmax + weighted gather ----------------
__global__ __launch_bounds__(256) void aggregate_kernel(
    const float* __restrict__ params, float* __restrict__ out,
    int D, const int* __restrict__ kptr, const int* __restrict__ mkptr)
{
    const int r = blockIdx.x;
    const int tid = threadIdx.x;
    const int k = eff_k(kptr, mkptr);

    __shared__ float w[MAXSEL];
    __shared__ int sidx[MAXSEL];

    for (int i = tid; i < k; i += blockDim.x) {
        w[i] = g_sel_score[r * MAXSEL + i];
        sidx[i] = g_sel_idx[r * MAXSEL + i];
    }
    __syncthreads();
    if (tid == 0) {
        float m = -3.402823e38f;
        for (int i = 0; i < k; i++) m = fmaxf(m, w[i]);
        float s = 0.f;
        for (int i = 0; i < k; i++) { w[i] = expf(w[i] - m); s += w[i]; }
        float inv = 1.0f / s;
        for (int i = 0; i < k; i++) w[i] *= inv;
    }
    __syncthreads();

    for (int d = tid; d < D; d += blockDim.x) {
        float a = 0.f;
        for (int i = 0; i < k; i++)
            a += w[i] * params[(size_t)sidx[i] * D + d];
        out[(size_t)r * D + d] = a;
    }
}

// ---------------- launch ----------------
extern "C" void kernel_launch(void* const* d_in, const int* in_sizes, int n_in,
                              void* d_out, int out_size)
{
    const float* hidden = (const float*)d_in[0];
    const float* params = (const float*)d_in[1];
    const float* keys   = (const float*)d_in[2];
    const float* W      = (const float*)d_in[3];
    const float* bias   = (const float*)d_in[4];
    const int*   kptr   = (const int*)d_in[5];
    const int*   mkptr  = (const int*)d_in[6];

    int D = (int)(sqrt((double)in_sizes[3]) + 0.5);   // W [D, D]
    int B = out_size / D;                              // out [B, D]
    int N = in_sizes[2] / D;                           // keys [N, D]
    int T = in_sizes[0] / (B * D);                     // hidden [B, T, D]
    float scale = 1.0f / sqrtf((float)D);

    float* out = (float*)d_out;

    cudaFuncSetAttribute(gemm_mma_kernel,
                         cudaFuncAttributeMaxDynamicSharedMemorySize, GEMM2_DYN);

    zero_scratch_kernel<<<(ROWS * NBIN + 255) / 256, 256>>>();
    pool_mean_kernel<<<(B * D + 255) / 256, 256>>>(hidden, B, T, D);
    query_projsplit_kernel<<<B, 256>>>(W, bias, D);
    gemm_mma_kernel<<<(N + TN - 1) / TN, 256, GEMM2_DYN>>>(keys, N, D, scale);
    hist_kernel<<<dim3(HCH, B), 256>>>(N);
    threshold_kernel<<<B, 256>>>(kptr, mkptr);
    compact_kernel<<<dim3(HCH, B), 256>>>(N);
    topk_final_kernel<<<B, SEL_T>>>(kptr, mkptr);
    aggregate_kernel<<<B, 256>>>(params, out, D, kptr, mkptr);
}

// round 17
// speedup vs baseline: 1.5976x; 1.5976x over previous
#include <cuda_runtime.h>
#include <cuda_bf16.h>
#include <math.h>
#include <stdint.h>

// ---------------- compile-time config ----------------
#define ROWS 32          // B (queries)
#define DMAX 1024
#define MAXSEL 1024
#define EQCAP 256
#define NBIN 4096
#define HCH 64
#define CAND 8192
#define TCH 4            // T-chunks for pool_mean

// mma GEMM tiling (R13-proven optimum: TN=96, 3 CTAs/SM)
#define TN 96            // keys per CTA
#define KC 64            // dims per chunk
#define ASW2 72          // A chunk smem row stride (bf16): 36 words = 4 mod 32 -> LDSM conflict-free
#define KSW 72           // key smem row stride (bf16)
#define A_CH_BYTES (64 * ASW2 * 2)      // 9216
#define KMAT_BYTES (TN * KSW * 2)       // 13824
#define STAGE_B (A_CH_BYTES + 2 * KMAT_BYTES)   // 36864
#define GEMM2_DYN (2 * STAGE_B + 256)           // 73984 -> 3 CTAs/SM

typedef unsigned long long ull;

// ---------------- scratch (device globals; no runtime allocation) ----------------
__device__ float g_poolp[TCH][ROWS * DMAX];      // pool partial sums
__device__ __nv_bfloat16 g_ab[64 * DMAX];        // rows 0-31: qh, rows 32-63: ql
__device__ float g_scores[(size_t)ROWS * 500224];
__device__ float g_sel_score[ROWS * MAXSEL];
__device__ int   g_sel_idx[ROWS * MAXSEL];
__device__ unsigned g_hist[ROWS][NBIN];
__device__ unsigned g_thr[ROWS];
__device__ int      g_ccnt[ROWS];
__device__ float    g_cscore[ROWS * CAND];
__device__ int      g_cidx[ROWS * CAND];

// ---------------- helpers ----------------
__device__ __forceinline__ void cpa16(void* dst_smem, const void* src) {
    unsigned s = (unsigned)__cvta_generic_to_shared(dst_smem);
    asm volatile("cp.async.cg.shared.global [%0], [%1], 16;" :: "r"(s), "l"(src) : "memory");
}
__device__ __forceinline__ void cp_commit() { asm volatile("cp.async.commit_group;" ::: "memory"); }
__device__ __forceinline__ void cp_wait0()  { asm volatile("cp.async.wait_group 0;" ::: "memory"); }

__device__ __forceinline__ unsigned flipf(float f) {
    unsigned u = __float_as_uint(f);
    return (u & 0x80000000u) ? ~u : (u | 0x80000000u);
}
__device__ __forceinline__ float unflipf(unsigned u) {
    return __uint_as_float((u & 0x80000000u) ? (u ^ 0x80000000u) : ~u);
}
__device__ __forceinline__ int eff_k(const int* kptr, const int* mkptr) {
    int k = kptr[0];
    int mk = mkptr[0];
    if (mk < k) k = mk;
    if (k < 1) k = 1;
    if (k > MAXSEL) k = MAXSEL;
    return k;
}
// pack two fp32 -> bf16x2, f0 in low half (element order)
__device__ __forceinline__ uint32_t pk_bf(float f0, float f1) {
    uint32_t r;
    asm("cvt.rn.bf16x2.f32 %0, %1, %2;" : "=r"(r) : "f"(f1), "f"(f0));
    return r;
}
__device__ __forceinline__ float bf_lo(uint32_t w) { return __uint_as_float(w << 16); }
__device__ __forceinline__ float bf_hi(uint32_t w) { return __uint_as_float(w & 0xFFFF0000u); }

// bf16 m16n8k16 tensor-core MMA
__device__ __forceinline__ void mma16816(float* c, const uint32_t* a, const uint32_t* b) {
    asm volatile("mma.sync.aligned.m16n8k16.row.col.f32.bf16.bf16.f32 "
                 "{%0,%1,%2,%3}, {%4,%5,%6,%7}, {%8,%9}, {%0,%1,%2,%3};"
                 : "+f"(c[0]), "+f"(c[1]), "+f"(c[2]), "+f"(c[3])
                 : "r"(a[0]), "r"(a[1]), "r"(a[2]), "r"(a[3]), "r"(b[0]), "r"(b[1]));
}
__device__ __forceinline__ void ldsm4(uint32_t* r, uint32_t addr) {
    asm volatile("ldmatrix.sync.aligned.m8n8.x4.shared.b16 {%0,%1,%2,%3}, [%4];"
                 : "=r"(r[0]), "=r"(r[1]), "=r"(r[2]), "=r"(r[3]) : "r"(addr));
}
__device__ __forceinline__ void ldsm2(uint32_t* r, uint32_t addr) {
    asm volatile("ldmatrix.sync.aligned.m8n8.x2.shared.b16 {%0,%1}, [%2];"
                 : "=r"(r[0]), "=r"(r[1]) : "r"(addr));
}

// ---------------- K1a: pooled partial sums over T-chunks (deterministic) ----------------
__global__ __launch_bounds__(256) void pool_mean_kernel(
    const float* __restrict__ hidden, int B, int T, int D)
{
    int gt = blockIdx.x * blockDim.x + threadIdx.x;
    if (gt >= B * D) return;
    int tc = blockIdx.y;
    int b = gt / D;
    int d = gt - b * D;
    int t0 = tc * (T / TCH);
    int t1 = (tc == TCH - 1) ? T : t0 + (T / TCH);
    const float* p = hidden + (size_t)b * T * D + d;
    float s = 0.f;
    #pragma unroll 8
    for (int t = t0; t < t1; t++) s += p[(size_t)t * D];
    g_poolp[tc][gt] = s;
}

// ---------------- K1b: query = pooled @ W + bias, split bf16 hi/lo -> g_ab ----------------
// grid (B, 2): each y-half handles D/2 output columns.
__global__ __launch_bounds__(256) void query_projsplit_kernel(
    const float* __restrict__ W, const float* __restrict__ bias, int D, float invT)
{
    int b = blockIdx.x;
    int half = blockIdx.y;
    int tid = threadIdx.x;
    __shared__ float sp[DMAX];
    for (int i = tid; i < D; i += blockDim.x) {
        float s = 0.f;
        #pragma unroll
        for (int tc = 0; tc < TCH; tc++) s += g_poolp[tc][b * D + i];
        sp[i] = s * invT;
    }
    __syncthreads();
    int d0 = half * (D / 2);
    int d1 = d0 + (D / 2);
    for (int d = d0 + tid; d < d1; d += blockDim.x) {
        float a = bias[d];
        #pragma unroll 8
        for (int kx = 0; kx < D; kx++) a += sp[kx] * W[(size_t)kx * D + d];
        __nv_bfloat16 h = __float2bfloat16(a);
        g_ab[b * D + d] = h;
        g_ab[(b + 32) * D + d] = __float2bfloat16(a - __bfloat162float(h));
    }
}

// ---------------- K2: split-bf16 tensor-core score GEMM (R13-exact) ----------------
extern __shared__ char gdyn[];
__global__ __launch_bounds__(256, 3) void gemm_mma_kernel(
    const float* __restrict__ keys, int N, int D, float scale)
{
    const int tid = threadIdx.x;
    const int lane = tid & 31;
    const int wid = tid >> 5;
    const int g = lane >> 2;        // 0..7
    const int tig = lane & 3;       // 0..3
    const int mt = wid >> 2;        // 0..1  (score rows mt*16..+15)
    const int nq = wid & 3;         // 0..3  (ntiles nq*3..+2)
    const long long nbase = (long long)blockIdx.x * TN;

    uint32_t raw;
    asm("{ .reg .u64 t; cvta.to.shared.u64 t, %1; cvt.u32.u64 %0, t; }" : "=r"(raw) : "l"(gdyn));
    char* base = gdyn + (((raw + 127u) & ~127u) - raw);
    const uint32_t base_u = (raw + 127u) & ~127u;

    __nv_bfloat16* Ast[2] = { (__nv_bfloat16*)base,
                              (__nv_bfloat16*)(base + STAGE_B) };
    __nv_bfloat16* KH[2]  = { (__nv_bfloat16*)(base + A_CH_BYTES),
                              (__nv_bfloat16*)(base + STAGE_B + A_CH_BYTES) };
    __nv_bfloat16* KL[2]  = { (__nv_bfloat16*)(base + A_CH_BYTES + KMAT_BYTES),
                              (__nv_bfloat16*)(base + STAGE_B + A_CH_BYTES + KMAT_BYTES) };

    const int nch = D / KC;

    const int aquad = lane >> 3;
    const int arow  = (aquad & 1) * 8 + (lane & 7);
    const int akoff = (aquad >> 1) * 8;
    const uint32_t a_off  = ((mt * 16 + arow) * ASW2 + akoff) * 2;
    const uint32_t AQL_D  = 32 * ASW2 * 2;
    const int bm    = lane >> 3;
    const int btile = bm >> 1;
    const int bkoff = (bm & 1) * 8;
    const int brow  = lane & 7;
    const uint32_t b_off_pair =
        (((nq * 3 + btile) * 8 + brow) * KSW + bkoff) * 2;
    const uint32_t b_off_sing =
        (((nq * 3 + 2) * 8 + (lane & 7)) * KSW + ((lane >> 3) & 1) * 8) * 2;

    auto load_A = [&](int st, int c) {
        #pragma unroll
        for (int it = 0; it < 2; it++) {
            int slot = tid + it * 256;        // 0..511
            int row = slot >> 3;              // 0..63
            int c16 = slot & 7;
            cpa16((char*)(Ast[st] + row * ASW2) + c16 * 16,
                  g_ab + (size_t)row * D + c * KC + c16 * 8);
        }
        cp_commit();
    };

    float acc[3][4];
    #pragma unroll
    for (int t = 0; t < 3; t++)
        #pragma unroll
        for (int j = 0; j < 4; j++) acc[t][j] = 0.f;

    load_A(0, 0);

    for (int c = 0; c < nch; c++) {
        const int st = c & 1;
        const uint32_t su = base_u + st * STAGE_B;

        // LDG fp32 keys -> bf16 hi/lo -> STS.64 (R13 pattern; 1536 slots, 6/thread)
        #pragma unroll
        for (int it = 0; it < 6; it++) {
            int slot = tid + it * 256;        // 0..1535
            int row = slot >> 4;              // 0..95
            int q4  = slot & 15;
            long long grow = nbase + row;
            if (grow >= N) grow = N - 1;
            float4 v = *(const float4*)(keys + grow * (long long)D + c * KC + q4 * 4);
            uint32_t h0 = pk_bf(v.x, v.y);
            uint32_t h1 = pk_bf(v.z, v.w);
            uint32_t l0 = pk_bf(v.x - bf_lo(h0), v.y - bf_hi(h0));
            uint32_t l1 = pk_bf(v.z - bf_lo(h1), v.w - bf_hi(h1));
            char* dh = (char*)(KH[st] + row * KSW) + q4 * 8;
            char* dl = (char*)(KL[st] + row * KSW) + q4 * 8;
            *(uint2*)dh = make_uint2(h0, h1);
            *(uint2*)dl = make_uint2(l0, l1);
        }
        cp_wait0();
        __syncthreads();
        if (c + 1 < nch) load_A(st ^ 1, c + 1);

        const uint32_t kh_u = su + A_CH_BYTES;
        const uint32_t kl_u = kh_u + KMAT_BYTES;
        #pragma unroll
        for (int ks = 0; ks < KC / 16; ks++) {
            const uint32_t kb = ks * 32;
            uint32_t aqh[4], aql[4];
            ldsm4(aqh, su + a_off + kb);
            ldsm4(aql, su + a_off + AQL_D + kb);
            {
                uint32_t bh[4], bl[4];
                ldsm4(bh, kh_u + b_off_pair + kb);
                ldsm4(bl, kl_u + b_off_pair + kb);
                mma16816(acc[0], aqh, bh + 0);
                mma16816(acc[0], aql, bh + 0);
                mma16816(acc[0], aqh, bl + 0);
                mma16816(acc[1], aqh, bh + 2);
                mma16816(acc[1], aql, bh + 2);
                mma16816(acc[1], aqh, bl + 2);
            }
            {
                uint32_t bh[2], bl[2];
                ldsm2(bh, kh_u + b_off_sing + kb);
                ldsm2(bl, kl_u + b_off_sing + kb);
                mma16816(acc[2], aqh, bh);
                mma16816(acc[2], aql, bh);
                mma16816(acc[2], aqh, bl);
            }
        }
    }

    #pragma unroll
    for (int t = 0; t < 3; t++) {
        const int nt = nq * 3 + t;
        long long col = nbase + nt * 8 + 2 * tig;
        int row0 = mt * 16 + g;
        if (col + 1 < N) {
            *(float2*)&g_scores[(size_t)row0 * N + col] =
                make_float2(acc[t][0] * scale, acc[t][1] * scale);
            *(float2*)&g_scores[(size_t)(row0 + 8) * N + col] =
                make_float2(acc[t][2] * scale, acc[t][3] * scale);
        } else if (col < N) {
            g_scores[(size_t)row0 * N + col] = acc[t][0] * scale;
            g_scores[(size_t)(row0 + 8) * N + col] = acc[t][2] * scale;
        }
    }
}

// ---------------- K3a: zero scratch ----------------
__global__ __launch_bounds__(256) void zero_scratch_kernel()
{
    int i = blockIdx.x * blockDim.x + threadIdx.x;
    if (i < ROWS * NBIN) ((unsigned*)g_hist)[i] = 0;
    if (i < ROWS) g_ccnt[i] = 0;
}

// aligned chunk size for the selection scans (multiple of 1024 floats)
__device__ __forceinline__ int chunk_per(int N) {
    return ((N + HCH * 1024 - 1) / (HCH * 1024)) * 1024;
}

// ---------------- K3b: grid-parallel per-row histogram (float4 scan) ----------------
__global__ __launch_bounds__(256) void hist_kernel(int N)
{
    const int r = blockIdx.y;
    const int c = blockIdx.x;
    const int tid = threadIdx.x;
    __shared__ unsigned sh[NBIN];
    for (int i = tid; i < NBIN; i += 256) sh[i] = 0;
    __syncthreads();

    const int per = chunk_per(N);
    const int s = c * per;
    const int e = (s + per < N) ? s + per : N;
    const float* srow = g_scores + (size_t)r * N;
    for (int i = s + tid * 4; i < e; i += 256 * 4) {
        if (i + 3 < e) {
            float4 v = *(const float4*)(srow + i);
            atomicAdd(&sh[flipf(v.x) >> 20], 1u);
            atomicAdd(&sh[flipf(v.y) >> 20], 1u);
            atomicAdd(&sh[flipf(v.z) >> 20], 1u);
            atomicAdd(&sh[flipf(v.w) >> 20], 1u);
        } else {
            for (int j = i; j < e; j++)
                atomicAdd(&sh[flipf(srow[j]) >> 20], 1u);
        }
    }
    __syncthreads();

    for (int i = tid; i < NBIN; i += 256)
        if (sh[i]) atomicAdd(&g_hist[r][i], sh[i]);
}

// ---------------- K3c: per-row threshold bin ----------------
__global__ __launch_bounds__(256) void threshold_kernel(
    const int* __restrict__ kptr, const int* __restrict__ mkptr)
{
    const int r = blockIdx.x;
    const int tid = threadIdx.x;
    __shared__ unsigned h[NBIN];
    __shared__ unsigned sfx[257];
    __shared__ int selg;

    const int k = eff_k(kptr, mkptr);
    for (int i = tid; i < NBIN; i += 256) h[i] = g_hist[r][i];
    __syncthreads();

    unsigned gsum = 0;
    #pragma unroll
    for (int b = 0; b < 16; b++) gsum += h[tid * 16 + b];
    sfx[tid] = gsum;
    if (tid == 0) sfx[256] = 0;
    __syncthreads();
    for (int off = 1; off < 256; off <<= 1) {
        unsigned t = (tid + off < 256) ? sfx[tid + off] : 0u;
        __syncthreads();
        sfx[tid] += t;
        __syncthreads();
    }
    unsigned above = (tid < 255) ? sfx[tid + 1] : 0u;
    if ((int)above < k && (int)sfx[tid] >= k) selg = tid;
    __syncthreads();

    if (tid == 0) {
        int g = selg;
        unsigned cum = (g < 255) ? sfx[g + 1] : 0u;
        int bsel = g * 16;
        for (int b = g * 16 + 15; b >= g * 16; b--) {
            cum += h[b];
            if ((int)cum >= k) { bsel = b; break; }
        }
        g_thr[r] = ((unsigned)bsel) << 20;
    }
}

// ---------------- K3d: compaction (float4 scan) ----------------
__global__ __launch_bounds__(256) void compact_kernel(int N)
{
    const int r = blockIdx.y;
    const int c = blockIdx.x;
    const int tid = threadIdx.x;
    const unsigned thr = g_thr[r];

    const int per = chunk_per(N);
    const int s = c * per;
    const int e = (s + per < N) ? s + per : N;
    const float* srow = g_scores + (size_t)r * N;
    for (int i = s + tid * 4; i < e; i += 256 * 4) {
        if (i + 3 < e) {
            float4 v = *(const float4*)(srow + i);
            float vv[4] = { v.x, v.y, v.z, v.w };
            #pragma unroll
            for (int j = 0; j < 4; j++) {
                if (flipf(vv[j]) >= thr) {
                    int p = atomicAdd(&g_ccnt[r], 1);
                    if (p < CAND) {
                        g_cscore[r * CAND + p] = vv[j];
                        g_cidx[r * CAND + p] = i + j;
                    }
                }
            }
        } else {
            for (int j = i; j < e; j++) {
                float v = srow[j];
                if (flipf(v) >= thr) {
                    int p = atomicAdd(&g_ccnt[r], 1);
                    if (p < CAND) {
                        g_cscore[r * CAND + p] = v;
                        g_cidx[r * CAND + p] = j;
                    }
                }
            }
        }
    }
}

// ---------------- K3e: exact top-k over candidates ----------------
#define SEL_T 256
__global__ __launch_bounds__(SEL_T) void topk_final_kernel(
    const int* __restrict__ kptr, const int* __restrict__ mkptr)
{
    const int r = blockIdx.x;
    const int tid = threadIdx.x;
    int M = g_ccnt[r];
    if (M > CAND) M = CAND;
    int k = eff_k(kptr, mkptr);
    if (k > M) k = M;

    const float* cs = g_cscore + r * CAND;
    const int*   ci = g_cidx + r * CAND;

    __shared__ unsigned bins[256];
    __shared__ unsigned sfx[257];
    __shared__ unsigned sh_prefix;
    __shared__ int sh_need;
    __shared__ int sh_selv;

    if (tid == 0) { sh_prefix = 0; sh_need = k; }
    __syncthreads();

    for (int pass = 0; pass < 4; pass++) {
        const int shift = 24 - 8 * pass;
        const unsigned hmask = pass ? (0xFFFFFFFFu << (shift + 8)) : 0u;
        bins[tid] = 0;
        __syncthreads();
        const unsigned pref = sh_prefix;
        for (int i = tid; i < M; i += SEL_T) {
            unsigned u = flipf(cs[i]);
            if ((u & hmask) == pref)
                atomicAdd(&bins[(u >> shift) & 255u], 1u);
        }
        __syncthreads();
        sfx[tid] = bins[tid];
        if (tid == 0) sfx[256] = 0;
        __syncthreads();
        for (int off = 1; off < 256; off <<= 1) {
            unsigned t = (tid + off < 256) ? sfx[tid + off] : 0u;
            __syncthreads();
            sfx[tid] += t;
            __syncthreads();
        }
        const int need = sh_need;
        const unsigned above = (tid < 255) ? sfx[tid + 1] : 0u;
        if ((int)above < need && (int)sfx[tid] >= need)
            sh_selv = tid;
        __syncthreads();
        if (tid == 0) {
            int v = sh_selv;
            sh_need = need - (int)((v < 255) ? sfx[v + 1] : 0u);
            sh_prefix = pref | ((unsigned)v << shift);
        }
        __syncthreads();
    }

    const unsigned uk = sh_prefix;
    const int need = sh_need;

    __shared__ int cg, ce;
    __shared__ int eq[EQCAP];
    if (tid == 0) { cg = 0; ce = 0; }
    __syncthreads();

    for (int i = tid; i < M; i += SEL_T) {
        unsigned u = flipf(cs[i]);
        if (u > uk) {
            int p = atomicAdd(&cg, 1);
            g_sel_score[r * MAXSEL + p] = cs[i];
            g_sel_idx[r * MAXSEL + p] = ci[i];
        } else if (u == uk) {
            int p = atomicAdd(&ce, 1);
            if (p < EQCAP) eq[p] = ci[i];
        }
    }
    __syncthreads();

    if (tid == 0) {
        const float tie_score = unflipf(uk);
        int base = cg;
        int ne = ce < EQCAP ? ce : EQCAP;
        for (int t = 0; t < need; t++) {
            int mv = 0x7FFFFFFF, mi = -1;
            for (int j = 0; j < ne; j++)
                if (eq[j] < mv) { mv = eq[j]; mi = j; }
            if (mi >= 0) eq[mi] = 0x7FFFFFFF;
            g_sel_idx[r * MAXSEL + base + t] = mv;
            g_sel_score[r * MAXSEL + base + t] = tie_score;
        }
        for (int a = 0; a < k - 1; a++) {
            int best = a;
            for (int bidx = a + 1; bidx < k; bidx++)
                if (g_sel_idx[r * MAXSEL + bidx] < g_sel_idx[r * MAXSEL + best]) best = bidx;
            if (best != a) {
                int ti = g_sel_idx[r * MAXSEL + a];
                g_sel_idx[r * MAXSEL + a] = g_sel_idx[r * MAXSEL + best];
                g_sel_idx[r * MAXSEL + best] = ti;
                float ts = g_sel_score[r * MAXSEL + a];
                g_sel_score[r * MAXSEL + a] = g_sel_score[r * MAXSEL + best];
                g_sel_score[r * MAXSEL + best] = ts;
            }
        }
    }
}

// ---------------- K4: softmax + weighted gather ----------------
__global__ __launch_bounds__(256) void aggregate_kernel(
    const float* __restrict__ params, float* __restrict__ out,
    int D, const int* __restrict__ kptr, const int* __restrict__ mkptr)
{
    const int r = blockIdx.x;
    const int tid = threadIdx.x;
    const int k = eff_k(kptr, mkptr);

    __shared__ float w[MAXSEL];
    __shared__ int sidx[MAXSEL];

    for (int i = tid; i < k; i += blockDim.x) {
        w[i] = g_sel_score[r * MAXSEL + i];
        sidx[i] = g_sel_idx[r * MAXSEL + i];
    }
    __syncthreads();
    if (tid == 0) {
        float m = -3.402823e38f;
        for (int i = 0; i < k; i++) m = fmaxf(m, w[i]);
        float s = 0.f;
        for (int i = 0; i < k; i++) { w[i] = expf(w[i] - m); s += w[i]; }
        float inv = 1.0f / s;
        for (int i = 0; i < k; i++) w[i] *= inv;
    }
    __syncthreads();

    for (int d = tid; d < D; d += blockDim.x) {
        float a = 0.f;
        for (int i = 0; i < k; i++)
            a += w[i] * params[(size_t)sidx[i] * D + d];
        out[(size_t)r * D + d] = a;
    }
}

// ---------------- launch ----------------
extern "C" void kernel_launch(void* const* d_in, const int* in_sizes, int n_in,
                              void* d_out, int out_size)
{
    const float* hidden = (const float*)d_in[0];
    const float* params = (const float*)d_in[1];
    const float* keys   = (const float*)d_in[2];
    const float* W      = (const float*)d_in[3];
    const float* bias   = (const float*)d_in[4];
    const int*   kptr   = (const int*)d_in[5];
    const int*   mkptr  = (const int*)d_in[6];

    int D = (int)(sqrt((double)in_sizes[3]) + 0.5);   // W [D, D]
    int B = out_size / D;                              // out [B, D]
    int N = in_sizes[2] / D;                           // keys [N, D]
    int T = in_sizes[0] / (B * D);                     // hidden [B, T, D]
    float scale = 1.0f / sqrtf((float)D);

    float* out = (float*)d_out;

    cudaFuncSetAttribute(gemm_mma_kernel,
                         cudaFuncAttributeMaxDynamicSharedMemorySize, GEMM2_DYN);

    zero_scratch_kernel<<<(ROWS * NBIN + 255) / 256, 256>>>();
    pool_mean_kernel<<<dim3((B * D + 255) / 256, TCH), 256>>>(hidden, B, T, D);
    query_projsplit_kernel<<<dim3(B, 2), 256>>>(W, bias, D, 1.0f / (float)T);
    gemm_mma_kernel<<<(N + TN - 1) / TN, 256, GEMM2_DYN>>>(keys, N, D, scale);
    hist_kernel<<<dim3(HCH, B), 256>>>(N);
    threshold_kernel<<<B, 256>>>(kptr, mkptr);
    compact_kernel<<<dim3(HCH, B), 256>>>(N);
    topk_final_kernel<<<B, SEL_T>>>(kptr, mkptr);
    aggregate_kernel<<<B, 256>>>(params, out, D, kptr, mkptr);
}